// round 1
// baseline (speedup 1.0000x reference)
#include <cuda_runtime.h>
#include <cuda_bf16.h>
#include <math.h>

// Problem constants
#define BSZ   2
#define LEN   2048
#define DIM   768
#define HDIM  1536
#define DSTATE 16
#define ROWS  (BSZ*LEN)          // 4096

// Output layout (concatenated flattened tuple):
//   [0 , 3145728)                        output [2,2048,768]
//   [3145728, 3145728+100663296)         hid    [2,2048,1536,16]
//   [103809024, 103809024+6287360)       a[...,1:] [2,2048,1535]
#define OUT0_OFF 0
#define OUT1_OFF (ROWS*DIM)                       // 3145728
#define OUT2_OFF (OUT1_OFF + (size_t)ROWS*HDIM*DSTATE)  // 103809024

// ---------------- scratch (device globals; no allocation allowed) ----------
__device__ float g_apre[ROWS * HDIM];   // x@W1+b1 (pre-conv)
__device__ float g_g   [ROWS * HDIM];   // silu(x@W2+b2)
__device__ float g_a   [ROWS * HDIM];   // silu(conv(a_pre))
__device__ float g_dl  [ROWS * HDIM];   // delta = softplus(...)
__device__ float g_bm  [ROWS * DSTATE]; // Bm

// ---------------- generic 128x128x8 fp32 SGEMM with fused epilogues --------
// C[M,N] = act( A[M,K] (optionally * A2 elementwise) @ B[K,N] + bias (+bias2) )
// MODE 0: identity, MODE 1: silu, MODE 2: softplus
// Requires M%128==0, N%128==0, K%8==0 (true for all uses here).
template<int MODE, bool HASA2>
__global__ void __launch_bounds__(256) sgemm128(
    const float* __restrict__ A, const float* __restrict__ A2,
    const float* __restrict__ B,
    const float* __restrict__ bias, const float* __restrict__ bias2,
    float* __restrict__ C, int M, int N, int K)
{
    __shared__ __align__(16) float As[8][128];
    __shared__ __align__(16) float Bs[8][128];

    const int bm = blockIdx.y * 128;
    const int bn = blockIdx.x * 128;
    const int tid = threadIdx.x;
    const int tx = tid & 15;     // column group 0..15
    const int ty = tid >> 4;     // row group 0..15

    float acc[8][8];
    #pragma unroll
    for (int i = 0; i < 8; i++)
        #pragma unroll
        for (int j = 0; j < 8; j++) acc[i][j] = 0.f;

    // A tile loader: 128 rows x 8 cols; each thread one float4
    const int arow = tid >> 1;          // 0..127
    const int acol = (tid & 1) * 4;     // 0 or 4
    // B tile loader: 8 rows x 128 cols; each thread one float4
    const int brow = tid >> 5;          // 0..7
    const int bcol = (tid & 31) * 4;    // 0..124

    const float* Aptr  = A  + (size_t)(bm + arow) * K + acol;
    const float* A2ptr = HASA2 ? (A2 + (size_t)(bm + arow) * K + acol) : nullptr;
    const float* Bptr  = B  + (size_t)brow * N + bn + bcol;

    for (int k0 = 0; k0 < K; k0 += 8) {
        float4 av = *(const float4*)(Aptr + k0);
        if (HASA2) {
            float4 a2 = *(const float4*)(A2ptr + k0);
            av.x *= a2.x; av.y *= a2.y; av.z *= a2.z; av.w *= a2.w;
        }
        As[acol + 0][arow] = av.x;
        As[acol + 1][arow] = av.y;
        As[acol + 2][arow] = av.z;
        As[acol + 3][arow] = av.w;
        float4 bv = *(const float4*)(Bptr + (size_t)k0 * N);
        *(float4*)&Bs[brow][bcol] = bv;
        __syncthreads();

        #pragma unroll
        for (int k = 0; k < 8; k++) {
            float4 a0 = *(const float4*)&As[k][ty * 8];
            float4 a1 = *(const float4*)&As[k][ty * 8 + 4];
            float4 b0 = *(const float4*)&Bs[k][tx * 8];
            float4 b1 = *(const float4*)&Bs[k][tx * 8 + 4];
            float ra[8] = {a0.x, a0.y, a0.z, a0.w, a1.x, a1.y, a1.z, a1.w};
            float rb[8] = {b0.x, b0.y, b0.z, b0.w, b1.x, b1.y, b1.z, b1.w};
            #pragma unroll
            for (int i = 0; i < 8; i++)
                #pragma unroll
                for (int j = 0; j < 8; j++)
                    acc[i][j] = fmaf(ra[i], rb[j], acc[i][j]);
        }
        __syncthreads();
    }

    // epilogue
    #pragma unroll
    for (int i = 0; i < 8; i++) {
        const int row = bm + ty * 8 + i;
        float* crow = C + (size_t)row * N + bn + tx * 8;
        float o[8];
        #pragma unroll
        for (int j = 0; j < 8; j++) {
            const int col = bn + tx * 8 + j;
            float v = acc[i][j] + bias[col];
            if (MODE == 2) v += bias2[col];
            if (MODE == 1) v = v / (1.f + expf(-v));                         // silu
            if (MODE == 2) v = fmaxf(v, 0.f) + log1pf(expf(-fabsf(v)));      // softplus
            o[j] = v;
        }
        *(float4*)(crow)     = make_float4(o[0], o[1], o[2], o[3]);
        *(float4*)(crow + 4) = make_float4(o[4], o[5], o[6], o[7]);
    }
}

// ---------------- depthwise causal conv1d (K=4) + silu ---------------------
__global__ void __launch_bounds__(256) conv_silu_kernel(
    const float* __restrict__ apre, const float* __restrict__ cw,
    const float* __restrict__ cb, float* __restrict__ a)
{
    const int idx = blockIdx.x * 256 + threadIdx.x;   // over ROWS*HDIM (exact)
    const int d = idx % HDIM;
    const int r = idx / HDIM;        // r = b*LEN + l
    const int l = r & (LEN - 1);
    float s = cb[d];
    #pragma unroll
    for (int j = 0; j < 4; j++) {
        const int ll = l - 3 + j;
        if (ll >= 0)
            s = fmaf(apre[(size_t)(r - 3 + j) * HDIM + d], cw[d * 4 + j], s);
    }
    a[idx] = s / (1.f + expf(-s));
}

// ---------------- skinny GEMM: Bm[r,s] = a[r,:] @ WB[:,s] + bB[s] ----------
__global__ void __launch_bounds__(256) gemm_wb_kernel(
    const float* __restrict__ a, const float* __restrict__ WB,
    const float* __restrict__ bB, float* __restrict__ Bm)
{
    const int r = blockIdx.x * 16 + (threadIdx.x >> 4);
    const int s = threadIdx.x & 15;
    const float* ar = a + (size_t)r * HDIM;
    float acc = 0.f;
    #pragma unroll 8
    for (int k = 0; k < HDIM; k++)
        acc = fmaf(__ldg(ar + k), __ldg(WB + k * DSTATE + s), acc);
    Bm[r * DSTATE + s] = acc + bB[s];
}

// ---------------- fused selective scan -> hid ------------------------------
// One 16-lane group per (b,d) channel; lane = state s. Never materializes
// A_/X_: h = exp(-A[d,s])*delta * h + Bm[b,l,s]*delta*a, streamed over l.
__global__ void __launch_bounds__(256) scan_kernel(
    const float* __restrict__ delta, const float* __restrict__ a,
    const float* __restrict__ Bm, const float* __restrict__ A,
    float* __restrict__ hid)
{
    const int g = blockIdx.x * 16 + (threadIdx.x >> 4); // channel over BSZ*HDIM
    const int s = threadIdx.x & 15;
    const int b = g / HDIM;
    const int d = g % HDIM;

    const float Ae = expf(-A[d * DSTATE + s]);
    float h = 0.f;

    const float* dptr = delta + (size_t)b * LEN * HDIM + d;
    const float* aptr = a     + (size_t)b * LEN * HDIM + d;
    const float* bptr = Bm    + (size_t)b * LEN * DSTATE + s;
    float* hptr = hid + ((size_t)b * LEN * HDIM + d) * DSTATE + s;

    for (int l0 = 0; l0 < LEN; l0 += 8) {
        float dv[8], av[8], bv[8];
        #pragma unroll
        for (int u = 0; u < 8; u++) {
            dv[u] = dptr[(size_t)(l0 + u) * HDIM];
            av[u] = aptr[(size_t)(l0 + u) * HDIM];
            bv[u] = bptr[(size_t)(l0 + u) * DSTATE];
        }
        #pragma unroll
        for (int u = 0; u < 8; u++) {
            h = fmaf(Ae * dv[u], h, bv[u] * dv[u] * av[u]);
            hptr[(size_t)(l0 + u) * (HDIM * DSTATE)] = h;
        }
    }
}

// ---------------- a[..., 1:] slice copy -------------------------------------
__global__ void __launch_bounds__(256) a_slice_kernel(
    const float* __restrict__ a, float* __restrict__ out)
{
    const size_t i = (size_t)blockIdx.x * 256 + threadIdx.x; // 4096*1535 exact
    const size_t r = i / (HDIM - 1);
    const size_t d = i % (HDIM - 1);
    out[i] = a[r * HDIM + d + 1];
}

// ---------------------------------------------------------------------------
extern "C" void kernel_launch(void* const* d_in, const int* in_sizes, int n_in,
                              void* d_out, int out_size)
{
    const float* x  = (const float*)d_in[0];
    const float* W1 = (const float*)d_in[1];
    const float* b1 = (const float*)d_in[2];
    const float* W2 = (const float*)d_in[3];
    const float* b2 = (const float*)d_in[4];
    const float* cw = (const float*)d_in[5];
    const float* cb = (const float*)d_in[6];
    const float* Wf = (const float*)d_in[7];
    const float* bf = (const float*)d_in[8];
    const float* A  = (const float*)d_in[9];
    const float* WB = (const float*)d_in[10];
    const float* bB = (const float*)d_in[11];
    // d_in[12] = WC, d_in[13] = bC : unused (reference overwrites that result)
    const float* WD = (const float*)d_in[14];
    const float* bD = (const float*)d_in[15];
    const float* Dv = (const float*)d_in[16];

    float* out = (float*)d_out;

    float *apre, *gg, *aa, *dl, *bm;
    cudaGetSymbolAddress((void**)&apre, g_apre);
    cudaGetSymbolAddress((void**)&gg,   g_g);
    cudaGetSymbolAddress((void**)&aa,   g_a);
    cudaGetSymbolAddress((void**)&dl,   g_dl);
    cudaGetSymbolAddress((void**)&bm,   g_bm);

    // 1) a_pre = x@W1 + b1            [4096,1536], K=768
    sgemm128<0,false><<<dim3(HDIM/128, ROWS/128), 256>>>(
        x, nullptr, W1, b1, nullptr, apre, ROWS, HDIM, DIM);
    // 2) g = silu(x@W2 + b2)
    sgemm128<1,false><<<dim3(HDIM/128, ROWS/128), 256>>>(
        x, nullptr, W2, b2, nullptr, gg, ROWS, HDIM, DIM);
    // 3) a = silu(causal depthwise conv(a_pre))
    conv_silu_kernel<<<(ROWS*HDIM)/256, 256>>>(apre, cw, cb, aa);
    // 4) delta = softplus(Dvec + a@WD + bD)   [4096,1536], K=1536
    sgemm128<2,false><<<dim3(HDIM/128, ROWS/128), 256>>>(
        aa, nullptr, WD, bD, Dv, dl, ROWS, HDIM, HDIM);
    // 5) Bm = a@WB + bB                [4096,16]
    gemm_wb_kernel<<<ROWS/16, 256>>>(aa, WB, bB, bm);
    // 6) output = (a*g)@Wf + bf        [4096,768] -> d_out section 0
    sgemm128<0,true><<<dim3(DIM/128, ROWS/128), 256>>>(
        aa, gg, Wf, bf, nullptr, out + OUT0_OFF, ROWS, DIM, HDIM);
    // 7) hid via fused selective scan  -> d_out section 1
    scan_kernel<<<(BSZ*HDIM)/16, 256>>>(dl, aa, bm, A, out + OUT1_OFF);
    // 8) a[..., 1:]                    -> d_out section 2
    a_slice_kernel<<<(ROWS*(HDIM-1))/256, 256>>>(aa, out + OUT2_OFF);
}

// round 3
// speedup vs baseline: 2.3341x; 2.3341x over previous
#include <cuda_runtime.h>
#include <math.h>
#include <stdint.h>

// ---------------- problem constants ----------------
#define BSZ    2
#define LEN    2048
#define DIM    768
#define HDIM   1536
#define DSTATE 16
#define ROWS   (BSZ*LEN)   // 4096

#define OUT0_OFF 0
#define OUT1_OFF ((size_t)ROWS*DIM)
#define OUT2_OFF (OUT1_OFF + (size_t)ROWS*HDIM*DSTATE)

// ---------------- scratch ----------------
__device__ float g_apre[ROWS * HDIM];
__device__ float g_g   [ROWS * HDIM];
__device__ float g_a   [ROWS * HDIM];
__device__ float g_ag  [ROWS * HDIM];
__device__ float g_dl  [ROWS * HDIM];
__device__ float g_bm  [ROWS * DSTATE];

// ---------------- PTX helpers ----------------
__device__ __forceinline__ uint32_t smem_u32(const void* p) {
    uint32_t a;
    asm("{ .reg .u64 t; cvta.to.shared.u64 t, %1; cvt.u32.u64 %0, t; }"
        : "=r"(a) : "l"(p));
    return a;
}
#define CP_ASYNC16(dst, src) \
    asm volatile("cp.async.cg.shared.global [%0], [%1], 16;" :: "r"(dst), "l"(src) : "memory")
#define CP_COMMIT()  asm volatile("cp.async.commit_group;" ::: "memory")
#define CP_WAIT1()   asm volatile("cp.async.wait_group 1;" ::: "memory")

__device__ __forceinline__ uint32_t f2tf32(float f) {
    uint32_t u;
    asm("cvt.rna.tf32.f32 %0, %1;" : "=r"(u) : "f"(f));
    return u;
}
__device__ __forceinline__ void mma_tf32(float* c, const uint32_t* a, const uint32_t* b) {
    asm volatile(
        "mma.sync.aligned.m16n8k8.row.col.f32.tf32.tf32.f32 "
        "{%0,%1,%2,%3}, {%4,%5,%6,%7}, {%8,%9}, {%0,%1,%2,%3};"
        : "+f"(c[0]), "+f"(c[1]), "+f"(c[2]), "+f"(c[3])
        : "r"(a[0]), "r"(a[1]), "r"(a[2]), "r"(a[3]), "r"(b[0]), "r"(b[1]));
}

// ---------------- TF32 tensor-core GEMM ----------------
// C[M,N] = act(A[M,K] @ B[K,N] + bias (+bias2))
// MODE 0: identity, 1: silu, 2: softplus(acc + bias + bias2)
// Requires M%128==0, N%128==0, K%32==0.
#define BK 32
#define ASTRIDE 36     // floats per A smem row (pad 4)
#define BSTRIDE 136    // floats per B smem row (pad 8)
#define A_FLOATS (128 * ASTRIDE)              // 4608
#define STAGE_FLOATS (A_FLOATS + BK * BSTRIDE) // 4608 + 4352 = 8960
#define GEMM_SMEM_BYTES (2 * STAGE_FLOATS * 4) // 71680

template<int MODE>
__global__ void __launch_bounds__(256, 1) tc_gemm(
    const float* __restrict__ A, const float* __restrict__ B,
    const float* __restrict__ bias, const float* __restrict__ bias2,
    float* __restrict__ C, int M, int N, int K)
{
    extern __shared__ float smem[];
    const uint32_t smem_b = smem_u32(smem);
    const int tid = threadIdx.x;
    const int wid = tid >> 5, lane = tid & 31;
    const int wm = wid >> 1, wn = wid & 1;      // 4x2 warp grid
    const int g = lane >> 2, t = lane & 3;
    const int bm = blockIdx.y * 128, bn = blockIdx.x * 128;

    // gmem->smem loader (cp.async, 16B)
    const int ar = tid >> 1;                    // A: 128 rows, 2 thr/row
    const int ac4 = (tid & 1) * 4;              // handles c4 and c4+... (2 chunks)
    const int bk = tid >> 5;                    // B: 8 rows per pass... use idx scheme below

    auto load_tile = [&](int t0, int s) {
        const int k0 = t0 * BK;
        const uint32_t abase = smem_b + (uint32_t)s * (STAGE_FLOATS * 4);
        const uint32_t bbase = abase + A_FLOATS * 4;
        #pragma unroll
        for (int i = 0; i < 4; i++) {           // A: 128x32 floats
            int idx = i * 256 + tid;
            int r = idx >> 3, c4 = idx & 7;
            CP_ASYNC16(abase + (uint32_t)(r * ASTRIDE + c4 * 4) * 4,
                       A + (size_t)(bm + r) * K + k0 + c4 * 4);
        }
        #pragma unroll
        for (int i = 0; i < 4; i++) {           // B: 32x128 floats
            int idx = i * 256 + tid;
            int kk = idx >> 5, c4 = idx & 31;
            CP_ASYNC16(bbase + (uint32_t)(kk * BSTRIDE + c4 * 4) * 4,
                       B + (size_t)(k0 + kk) * N + bn + c4 * 4);
        }
    };

    float acc[2][8][4];
    #pragma unroll
    for (int mi = 0; mi < 2; mi++)
        #pragma unroll
        for (int nj = 0; nj < 8; nj++)
            #pragma unroll
            for (int q = 0; q < 4; q++) acc[mi][nj][q] = 0.f;

    const int T = K / BK;
    load_tile(0, 0);
    CP_COMMIT();

    for (int tt = 0; tt < T; tt++) {
        if (tt + 1 < T) load_tile(tt + 1, (tt + 1) & 1);
        CP_COMMIT();
        CP_WAIT1();
        __syncthreads();

        const float* As = smem + (tt & 1) * STAGE_FLOATS;
        const float* Bs = As + A_FLOATS;

        #pragma unroll
        for (int kk = 0; kk < 4; kk++) {
            uint32_t af[2][4];
            #pragma unroll
            for (int mi = 0; mi < 2; mi++) {
                const float* ap = As + (wm * 32 + mi * 16 + g) * ASTRIDE + kk * 8 + t;
                af[mi][0] = f2tf32(ap[0]);
                af[mi][1] = f2tf32(ap[8 * ASTRIDE]);
                af[mi][2] = f2tf32(ap[4]);
                af[mi][3] = f2tf32(ap[8 * ASTRIDE + 4]);
            }
            uint32_t bf[8][2];
            #pragma unroll
            for (int nj = 0; nj < 8; nj++) {
                const float* bp = Bs + (kk * 8 + t) * BSTRIDE + wn * 64 + nj * 8 + g;
                bf[nj][0] = f2tf32(bp[0]);
                bf[nj][1] = f2tf32(bp[4 * BSTRIDE]);
            }
            #pragma unroll
            for (int mi = 0; mi < 2; mi++)
                #pragma unroll
                for (int nj = 0; nj < 8; nj++)
                    mma_tf32(acc[mi][nj], af[mi], bf[nj]);
        }
        __syncthreads();
    }

    // epilogue
    #pragma unroll
    for (int mi = 0; mi < 2; mi++) {
        const int row0 = bm + wm * 32 + mi * 16 + g;
        #pragma unroll
        for (int nj = 0; nj < 8; nj++) {
            const int col = bn + wn * 64 + nj * 8 + t * 2;
            const float bz0 = __ldg(bias + col), bz1 = __ldg(bias + col + 1);
            float e0 = (MODE == 2) ? __ldg(bias2 + col) : 0.f;
            float e1 = (MODE == 2) ? __ldg(bias2 + col + 1) : 0.f;
            float v[4];
            v[0] = acc[mi][nj][0] + bz0 + e0;
            v[1] = acc[mi][nj][1] + bz1 + e1;
            v[2] = acc[mi][nj][2] + bz0 + e0;
            v[3] = acc[mi][nj][3] + bz1 + e1;
            #pragma unroll
            for (int q = 0; q < 4; q++) {
                if (MODE == 1) v[q] = v[q] / (1.f + expf(-v[q]));
                if (MODE == 2) v[q] = fmaxf(v[q], 0.f) + log1pf(expf(-fabsf(v[q])));
            }
            *(float2*)(C + (size_t)row0 * N + col)       = make_float2(v[0], v[1]);
            *(float2*)(C + (size_t)(row0 + 8) * N + col) = make_float2(v[2], v[3]);
        }
    }
}

// ---------------- conv(K=4)+silu, fused a*g and a[...,1:] slice -------------
__global__ void __launch_bounds__(256) conv_fuse_kernel(
    const float* __restrict__ apre, const float* __restrict__ cw,
    const float* __restrict__ cb, const float* __restrict__ g,
    float* __restrict__ aa, float* __restrict__ ag, float* __restrict__ out2)
{
    const int idx = blockIdx.x * 256 + threadIdx.x;
    const int d = idx % HDIM;
    const int r = idx / HDIM;
    const int l = r & (LEN - 1);
    float s = cb[d];
    #pragma unroll
    for (int j = 0; j < 4; j++) {
        const int ll = l - 3 + j;
        if (ll >= 0)
            s = fmaf(apre[(size_t)(r - 3 + j) * HDIM + d], cw[d * 4 + j], s);
    }
    const float a = s / (1.f + expf(-s));
    aa[idx] = a;
    ag[idx] = a * g[idx];
    if (d >= 1) out2[(size_t)r * (HDIM - 1) + d - 1] = a;
}

// ---------------- Bm = a @ WB + bB (warp per row, shfl reduce) --------------
__global__ void __launch_bounds__(256) wb_kernel(
    const float* __restrict__ a, const float* __restrict__ WB,
    const float* __restrict__ bB, float* __restrict__ Bm)
{
    const int wid = threadIdx.x >> 5, lane = threadIdx.x & 31;
    const int r = blockIdx.x * 8 + wid;
    const float* ar = a + (size_t)r * HDIM;
    float acc[16];
    #pragma unroll
    for (int s = 0; s < 16; s++) acc[s] = 0.f;
    for (int k = lane; k < HDIM; k += 32) {
        const float av = ar[k];
        const float4* w = (const float4*)(WB + (size_t)k * 16);
        float4 w0 = w[0], w1 = w[1], w2 = w[2], w3 = w[3];
        acc[0]  = fmaf(av, w0.x, acc[0]);  acc[1]  = fmaf(av, w0.y, acc[1]);
        acc[2]  = fmaf(av, w0.z, acc[2]);  acc[3]  = fmaf(av, w0.w, acc[3]);
        acc[4]  = fmaf(av, w1.x, acc[4]);  acc[5]  = fmaf(av, w1.y, acc[5]);
        acc[6]  = fmaf(av, w1.z, acc[6]);  acc[7]  = fmaf(av, w1.w, acc[7]);
        acc[8]  = fmaf(av, w2.x, acc[8]);  acc[9]  = fmaf(av, w2.y, acc[9]);
        acc[10] = fmaf(av, w2.z, acc[10]); acc[11] = fmaf(av, w2.w, acc[11]);
        acc[12] = fmaf(av, w3.x, acc[12]); acc[13] = fmaf(av, w3.y, acc[13]);
        acc[14] = fmaf(av, w3.z, acc[14]); acc[15] = fmaf(av, w3.w, acc[15]);
    }
    #pragma unroll
    for (int off = 16; off >= 1; off >>= 1)
        #pragma unroll
        for (int s = 0; s < 16; s++)
            acc[s] += __shfl_xor_sync(0xFFFFFFFF, acc[s], off);
    if (lane < 16) Bm[r * 16 + lane] = acc[lane] + bB[lane];
}

// ---------------- fused selective scan -> hid ----------------
__global__ void __launch_bounds__(256) scan_kernel(
    const float* __restrict__ delta, const float* __restrict__ a,
    const float* __restrict__ Bm, const float* __restrict__ A,
    float* __restrict__ hid)
{
    const int g = blockIdx.x * 16 + (threadIdx.x >> 4);
    const int s = threadIdx.x & 15;
    const int b = g / HDIM;
    const int d = g % HDIM;

    const float Ae = expf(-A[d * DSTATE + s]);
    float h = 0.f;

    const float* dptr = delta + (size_t)b * LEN * HDIM + d;
    const float* aptr = a     + (size_t)b * LEN * HDIM + d;
    const float* bptr = Bm    + (size_t)b * LEN * DSTATE + s;
    float* hptr = hid + ((size_t)b * LEN * HDIM + d) * DSTATE + s;

    for (int l0 = 0; l0 < LEN; l0 += 8) {
        float dv[8], av[8], bv[8];
        #pragma unroll
        for (int u = 0; u < 8; u++) {
            dv[u] = dptr[(size_t)(l0 + u) * HDIM];
            av[u] = aptr[(size_t)(l0 + u) * HDIM];
            bv[u] = bptr[(size_t)(l0 + u) * DSTATE];
        }
        #pragma unroll
        for (int u = 0; u < 8; u++) {
            h = fmaf(Ae * dv[u], h, bv[u] * dv[u] * av[u]);
            hptr[(size_t)(l0 + u) * (HDIM * DSTATE)] = h;
        }
    }
}

// ---------------------------------------------------------------------------
extern "C" void kernel_launch(void* const* d_in, const int* in_sizes, int n_in,
                              void* d_out, int out_size)
{
    const float* x  = (const float*)d_in[0];
    const float* W1 = (const float*)d_in[1];
    const float* b1 = (const float*)d_in[2];
    const float* W2 = (const float*)d_in[3];
    const float* b2 = (const float*)d_in[4];
    const float* cw = (const float*)d_in[5];
    const float* cb = (const float*)d_in[6];
    const float* Wf = (const float*)d_in[7];
    const float* bf = (const float*)d_in[8];
    const float* A  = (const float*)d_in[9];
    const float* WB = (const float*)d_in[10];
    const float* bB = (const float*)d_in[11];
    const float* WD = (const float*)d_in[14];
    const float* bD = (const float*)d_in[15];
    const float* Dv = (const float*)d_in[16];

    float* out = (float*)d_out;

    float *apre, *gg, *aa, *ag, *dl, *bm;
    cudaGetSymbolAddress((void**)&apre, g_apre);
    cudaGetSymbolAddress((void**)&gg,   g_g);
    cudaGetSymbolAddress((void**)&aa,   g_a);
    cudaGetSymbolAddress((void**)&ag,   g_ag);
    cudaGetSymbolAddress((void**)&dl,   g_dl);
    cudaGetSymbolAddress((void**)&bm,   g_bm);

    cudaFuncSetAttribute(tc_gemm<0>, cudaFuncAttributeMaxDynamicSharedMemorySize, GEMM_SMEM_BYTES);
    cudaFuncSetAttribute(tc_gemm<1>, cudaFuncAttributeMaxDynamicSharedMemorySize, GEMM_SMEM_BYTES);
    cudaFuncSetAttribute(tc_gemm<2>, cudaFuncAttributeMaxDynamicSharedMemorySize, GEMM_SMEM_BYTES);

    // 1) a_pre = x@W1 + b1
    tc_gemm<0><<<dim3(HDIM/128, ROWS/128), 256, GEMM_SMEM_BYTES>>>(
        x, W1, b1, nullptr, apre, ROWS, HDIM, DIM);
    // 2) g = silu(x@W2 + b2)
    tc_gemm<1><<<dim3(HDIM/128, ROWS/128), 256, GEMM_SMEM_BYTES>>>(
        x, W2, b2, nullptr, gg, ROWS, HDIM, DIM);
    // 3) a = silu(conv(a_pre)); ag = a*g; out2 = a[...,1:]
    conv_fuse_kernel<<<(ROWS*HDIM)/256, 256>>>(apre, cw, cb, gg, aa, ag, out + OUT2_OFF);
    // 4) delta = softplus(Dvec + a@WD + bD)
    tc_gemm<2><<<dim3(HDIM/128, ROWS/128), 256, GEMM_SMEM_BYTES>>>(
        aa, WD, bD, Dv, dl, ROWS, HDIM, HDIM);
    // 5) Bm = a@WB + bB
    wb_kernel<<<ROWS/8, 256>>>(aa, WB, bB, bm);
    // 6) output = (a*g)@Wf + bf
    tc_gemm<0><<<dim3(DIM/128, ROWS/128), 256, GEMM_SMEM_BYTES>>>(
        ag, Wf, bf, nullptr, out + OUT0_OFF, ROWS, DIM, HDIM);
    // 7) hid via fused selective scan
    scan_kernel<<<(BSZ*HDIM)/16, 256>>>(dl, aa, bm, A, out + OUT1_OFF);
}

// round 4
// speedup vs baseline: 2.3473x; 1.0056x over previous
#include <cuda_runtime.h>
#include <math.h>
#include <stdint.h>

// ---------------- problem constants ----------------
#define BSZ    2
#define LEN    2048
#define DIM    768
#define HDIM   1536
#define DSTATE 16
#define ROWS   (BSZ*LEN)   // 4096

#define OUT0_OFF 0
#define OUT1_OFF ((size_t)ROWS*DIM)
#define OUT2_OFF (OUT1_OFF + (size_t)ROWS*HDIM*DSTATE)

// ---------------- scratch ----------------
__device__ float g_apre[ROWS * HDIM];   // x@W1+b1
__device__ float g_g   [ROWS * HDIM];   // silu(x@W2+b2)
__device__ float g_a   [ROWS * HDIM];   // fp32 a (for scan / wb / slice)
__device__ float g_aat [ROWS * HDIM];   // tf32-rounded a   (WD GEMM input)
__device__ float g_agt [ROWS * HDIM];   // tf32-rounded a*g (Wf GEMM input)
__device__ float g_dl  [ROWS * HDIM];   // delta
__device__ float g_bm  [ROWS * DSTATE]; // Bm
// tf32-rounded copies of x and weights
__device__ float g_xt  [ROWS * DIM];
__device__ float g_w1t [DIM * HDIM];
__device__ float g_w2t [DIM * HDIM];
__device__ float g_wdt [HDIM * HDIM];
__device__ float g_wft [HDIM * DIM];

// ---------------- PTX helpers ----------------
__device__ __forceinline__ uint32_t smem_u32(const void* p) {
    uint32_t a;
    asm("{ .reg .u64 t; cvta.to.shared.u64 t, %1; cvt.u32.u64 %0, t; }"
        : "=r"(a) : "l"(p));
    return a;
}
#define CP_ASYNC16(dst, src) \
    asm volatile("cp.async.cg.shared.global [%0], [%1], 16;" :: "r"(dst), "l"(src) : "memory")
#define CP_COMMIT()  asm volatile("cp.async.commit_group;" ::: "memory")
#define CP_WAIT1()   asm volatile("cp.async.wait_group 1;" ::: "memory")

__device__ __forceinline__ float rnd_tf32(float f) {
    uint32_t u;
    asm("cvt.rna.tf32.f32 %0, %1;" : "=r"(u) : "f"(f));
    return __uint_as_float(u);
}
__device__ __forceinline__ void mma_tf32(float* c, const uint32_t* a, const uint32_t* b) {
    asm volatile(
        "mma.sync.aligned.m16n8k8.row.col.f32.tf32.tf32.f32 "
        "{%0,%1,%2,%3}, {%4,%5,%6,%7}, {%8,%9}, {%0,%1,%2,%3};"
        : "+f"(c[0]), "+f"(c[1]), "+f"(c[2]), "+f"(c[3])
        : "r"(a[0]), "r"(a[1]), "r"(a[2]), "r"(a[3]), "r"(b[0]), "r"(b[1]));
}

// ---------------- pre-round x + all weights to tf32 ----------------
#define XT4  (ROWS*DIM/4)
#define W14  (DIM*HDIM/4)
#define WD4  (HDIM*HDIM/4)
#define RB0  XT4
#define RB1  (RB0 + W14)
#define RB2  (RB1 + W14)
#define RB3  (RB2 + WD4)
#define RTOT (RB3 + W14)   // 2260992

__global__ void __launch_bounds__(256) round_all_kernel(
    const float4* __restrict__ x,  const float4* __restrict__ w1,
    const float4* __restrict__ w2, const float4* __restrict__ wd,
    const float4* __restrict__ wf,
    float4* __restrict__ xt,  float4* __restrict__ w1t,
    float4* __restrict__ w2t, float4* __restrict__ wdt,
    float4* __restrict__ wft)
{
    int i = blockIdx.x * 256 + threadIdx.x;
    if (i >= RTOT) return;
    const float4* s; float4* d; int off;
    if      (i < RB0) { s = x;  d = xt;  off = i; }
    else if (i < RB1) { s = w1; d = w1t; off = i - RB0; }
    else if (i < RB2) { s = w2; d = w2t; off = i - RB1; }
    else if (i < RB3) { s = wd; d = wdt; off = i - RB2; }
    else              { s = wf; d = wft; off = i - RB3; }
    float4 v = s[off];
    v.x = rnd_tf32(v.x); v.y = rnd_tf32(v.y);
    v.z = rnd_tf32(v.z); v.w = rnd_tf32(v.w);
    d[off] = v;
}

// ---------------- TF32 tensor-core GEMM (pre-rounded operands) -------------
// C[M,N] = act(A[M,K] @ B[K,N] + bias (+bias2))
// MODE 0: identity, 1: silu, 2: softplus(acc + bias + bias2)
#define BK 32
#define ASTRIDE 36
#define BSTRIDE 136
#define A_FLOATS (128 * ASTRIDE)
#define STAGE_FLOATS (A_FLOATS + BK * BSTRIDE)
#define GEMM_SMEM_BYTES (2 * STAGE_FLOATS * 4)

template<int MODE>
__global__ void __launch_bounds__(256, 1) tc_gemm(
    const float* __restrict__ A, const float* __restrict__ B,
    const float* __restrict__ bias, const float* __restrict__ bias2,
    float* __restrict__ C, int M, int N, int K)
{
    extern __shared__ float smem[];
    const uint32_t smem_b = smem_u32(smem);
    const int tid = threadIdx.x;
    const int wid = tid >> 5, lane = tid & 31;
    const int wm = wid >> 1, wn = wid & 1;      // 4x2 warp grid, 32x64 warp tile
    const int g = lane >> 2, t = lane & 3;
    const int bm = blockIdx.y * 128, bn = blockIdx.x * 128;

    auto load_tile = [&](int t0, int s) {
        const int k0 = t0 * BK;
        const uint32_t abase = smem_b + (uint32_t)s * (STAGE_FLOATS * 4);
        const uint32_t bbase = abase + A_FLOATS * 4;
        #pragma unroll
        for (int i = 0; i < 4; i++) {
            int idx = i * 256 + tid;
            int r = idx >> 3, c4 = idx & 7;
            CP_ASYNC16(abase + (uint32_t)(r * ASTRIDE + c4 * 4) * 4,
                       A + (size_t)(bm + r) * K + k0 + c4 * 4);
        }
        #pragma unroll
        for (int i = 0; i < 4; i++) {
            int idx = i * 256 + tid;
            int kk = idx >> 5, c4 = idx & 31;
            CP_ASYNC16(bbase + (uint32_t)(kk * BSTRIDE + c4 * 4) * 4,
                       B + (size_t)(k0 + kk) * N + bn + c4 * 4);
        }
    };

    float acc[2][8][4];
    #pragma unroll
    for (int mi = 0; mi < 2; mi++)
        #pragma unroll
        for (int nj = 0; nj < 8; nj++)
            #pragma unroll
            for (int q = 0; q < 4; q++) acc[mi][nj][q] = 0.f;

    const int T = K / BK;
    load_tile(0, 0);
    CP_COMMIT();

    for (int tt = 0; tt < T; tt++) {
        if (tt + 1 < T) load_tile(tt + 1, (tt + 1) & 1);
        CP_COMMIT();
        CP_WAIT1();
        __syncthreads();

        const float* As = smem + (tt & 1) * STAGE_FLOATS;
        const float* Bs = As + A_FLOATS;

        #pragma unroll
        for (int kk = 0; kk < 4; kk++) {
            uint32_t af[2][4];
            #pragma unroll
            for (int mi = 0; mi < 2; mi++) {
                const float* ap = As + (wm * 32 + mi * 16 + g) * ASTRIDE + kk * 8 + t;
                af[mi][0] = __float_as_uint(ap[0]);
                af[mi][1] = __float_as_uint(ap[8 * ASTRIDE]);
                af[mi][2] = __float_as_uint(ap[4]);
                af[mi][3] = __float_as_uint(ap[8 * ASTRIDE + 4]);
            }
            uint32_t bf[8][2];
            #pragma unroll
            for (int nj = 0; nj < 8; nj++) {
                const float* bp = Bs + (kk * 8 + t) * BSTRIDE + wn * 64 + nj * 8 + g;
                bf[nj][0] = __float_as_uint(bp[0]);
                bf[nj][1] = __float_as_uint(bp[4 * BSTRIDE]);
            }
            #pragma unroll
            for (int mi = 0; mi < 2; mi++)
                #pragma unroll
                for (int nj = 0; nj < 8; nj++)
                    mma_tf32(acc[mi][nj], af[mi], bf[nj]);
        }
        __syncthreads();
    }

    // epilogue
    #pragma unroll
    for (int nj = 0; nj < 8; nj++) {
        const int col = bn + wn * 64 + nj * 8 + t * 2;
        const float bz0 = __ldg(bias + col), bz1 = __ldg(bias + col + 1);
        const float e0 = (MODE == 2) ? __ldg(bias2 + col) : 0.f;
        const float e1 = (MODE == 2) ? __ldg(bias2 + col + 1) : 0.f;
        #pragma unroll
        for (int mi = 0; mi < 2; mi++) {
            const int row0 = bm + wm * 32 + mi * 16 + g;
            float v[4];
            v[0] = acc[mi][nj][0] + bz0 + e0;
            v[1] = acc[mi][nj][1] + bz1 + e1;
            v[2] = acc[mi][nj][2] + bz0 + e0;
            v[3] = acc[mi][nj][3] + bz1 + e1;
            #pragma unroll
            for (int q = 0; q < 4; q++) {
                if (MODE == 1) v[q] = v[q] / (1.f + expf(-v[q]));
                if (MODE == 2) v[q] = fmaxf(v[q], 0.f) + log1pf(expf(-fabsf(v[q])));
            }
            *(float2*)(C + (size_t)row0 * N + col)       = make_float2(v[0], v[1]);
            *(float2*)(C + (size_t)(row0 + 8) * N + col) = make_float2(v[2], v[3]);
        }
    }
}

// ---------------- conv(K=4)+silu; writes a, tf32(a), tf32(a*g), slice ------
__global__ void __launch_bounds__(256) conv_fuse_kernel(
    const float* __restrict__ apre, const float* __restrict__ cw,
    const float* __restrict__ cb, const float* __restrict__ g,
    float* __restrict__ aa, float* __restrict__ aat,
    float* __restrict__ agt, float* __restrict__ out2)
{
    const int idx = blockIdx.x * 256 + threadIdx.x;
    const int d = idx % HDIM;
    const int r = idx / HDIM;
    const int l = r & (LEN - 1);
    float s = cb[d];
    #pragma unroll
    for (int j = 0; j < 4; j++) {
        const int ll = l - 3 + j;
        if (ll >= 0)
            s = fmaf(apre[(size_t)(r - 3 + j) * HDIM + d], cw[d * 4 + j], s);
    }
    const float a = s / (1.f + expf(-s));
    aa[idx]  = a;
    aat[idx] = rnd_tf32(a);
    agt[idx] = rnd_tf32(a * g[idx]);
    if (d >= 1) out2[(size_t)r * (HDIM - 1) + d - 1] = a;
}

// ---------------- Bm = a @ WB + bB (warp per row, shfl reduce) --------------
__global__ void __launch_bounds__(256) wb_kernel(
    const float* __restrict__ a, const float* __restrict__ WB,
    const float* __restrict__ bB, float* __restrict__ Bm)
{
    const int wid = threadIdx.x >> 5, lane = threadIdx.x & 31;
    const int r = blockIdx.x * 8 + wid;
    const float* ar = a + (size_t)r * HDIM;
    float acc[16];
    #pragma unroll
    for (int s = 0; s < 16; s++) acc[s] = 0.f;
    for (int k = lane; k < HDIM; k += 32) {
        const float av = ar[k];
        const float4* w = (const float4*)(WB + (size_t)k * 16);
        float4 w0 = w[0], w1 = w[1], w2 = w[2], w3 = w[3];
        acc[0]  = fmaf(av, w0.x, acc[0]);  acc[1]  = fmaf(av, w0.y, acc[1]);
        acc[2]  = fmaf(av, w0.z, acc[2]);  acc[3]  = fmaf(av, w0.w, acc[3]);
        acc[4]  = fmaf(av, w1.x, acc[4]);  acc[5]  = fmaf(av, w1.y, acc[5]);
        acc[6]  = fmaf(av, w1.z, acc[6]);  acc[7]  = fmaf(av, w1.w, acc[7]);
        acc[8]  = fmaf(av, w2.x, acc[8]);  acc[9]  = fmaf(av, w2.y, acc[9]);
        acc[10] = fmaf(av, w2.z, acc[10]); acc[11] = fmaf(av, w2.w, acc[11]);
        acc[12] = fmaf(av, w3.x, acc[12]); acc[13] = fmaf(av, w3.y, acc[13]);
        acc[14] = fmaf(av, w3.z, acc[14]); acc[15] = fmaf(av, w3.w, acc[15]);
    }
    #pragma unroll
    for (int off = 16; off >= 1; off >>= 1)
        #pragma unroll
        for (int s = 0; s < 16; s++)
            acc[s] += __shfl_xor_sync(0xFFFFFFFF, acc[s], off);
    if (lane < 16) Bm[r * 16 + lane] = acc[lane] + bB[lane];
}

// ---------------- fused selective scan -> hid ----------------
__global__ void __launch_bounds__(256) scan_kernel(
    const float* __restrict__ delta, const float* __restrict__ a,
    const float* __restrict__ Bm, const float* __restrict__ A,
    float* __restrict__ hid)
{
    const int g = blockIdx.x * 16 + (threadIdx.x >> 4);
    const int s = threadIdx.x & 15;
    const int b = g / HDIM;
    const int d = g % HDIM;

    const float Ae = expf(-A[d * DSTATE + s]);
    float h = 0.f;

    const float* dptr = delta + (size_t)b * LEN * HDIM + d;
    const float* aptr = a     + (size_t)b * LEN * HDIM + d;
    const float* bptr = Bm    + (size_t)b * LEN * DSTATE + s;
    float* hptr = hid + ((size_t)b * LEN * HDIM + d) * DSTATE + s;

    for (int l0 = 0; l0 < LEN; l0 += 8) {
        float dv[8], av[8], bv[8];
        #pragma unroll
        for (int u = 0; u < 8; u++) {
            dv[u] = dptr[(size_t)(l0 + u) * HDIM];
            av[u] = aptr[(size_t)(l0 + u) * HDIM];
            bv[u] = bptr[(size_t)(l0 + u) * DSTATE];
        }
        #pragma unroll
        for (int u = 0; u < 8; u++) {
            h = fmaf(Ae * dv[u], h, bv[u] * dv[u] * av[u]);
            hptr[(size_t)(l0 + u) * (HDIM * DSTATE)] = h;
        }
    }
}

// ---------------------------------------------------------------------------
extern "C" void kernel_launch(void* const* d_in, const int* in_sizes, int n_in,
                              void* d_out, int out_size)
{
    const float* x  = (const float*)d_in[0];
    const float* W1 = (const float*)d_in[1];
    const float* b1 = (const float*)d_in[2];
    const float* W2 = (const float*)d_in[3];
    const float* b2 = (const float*)d_in[4];
    const float* cw = (const float*)d_in[5];
    const float* cb = (const float*)d_in[6];
    const float* Wf = (const float*)d_in[7];
    const float* bf = (const float*)d_in[8];
    const float* A  = (const float*)d_in[9];
    const float* WB = (const float*)d_in[10];
    const float* bB = (const float*)d_in[11];
    const float* WD = (const float*)d_in[14];
    const float* bD = (const float*)d_in[15];
    const float* Dv = (const float*)d_in[16];

    float* out = (float*)d_out;

    float *apre, *gg, *aa, *aat, *agt, *dl, *bm;
    float *xt, *w1t, *w2t, *wdt, *wft;
    cudaGetSymbolAddress((void**)&apre, g_apre);
    cudaGetSymbolAddress((void**)&gg,   g_g);
    cudaGetSymbolAddress((void**)&aa,   g_a);
    cudaGetSymbolAddress((void**)&aat,  g_aat);
    cudaGetSymbolAddress((void**)&agt,  g_agt);
    cudaGetSymbolAddress((void**)&dl,   g_dl);
    cudaGetSymbolAddress((void**)&bm,   g_bm);
    cudaGetSymbolAddress((void**)&xt,   g_xt);
    cudaGetSymbolAddress((void**)&w1t,  g_w1t);
    cudaGetSymbolAddress((void**)&w2t,  g_w2t);
    cudaGetSymbolAddress((void**)&wdt,  g_wdt);
    cudaGetSymbolAddress((void**)&wft,  g_wft);

    cudaFuncSetAttribute(tc_gemm<0>, cudaFuncAttributeMaxDynamicSharedMemorySize, GEMM_SMEM_BYTES);
    cudaFuncSetAttribute(tc_gemm<1>, cudaFuncAttributeMaxDynamicSharedMemorySize, GEMM_SMEM_BYTES);
    cudaFuncSetAttribute(tc_gemm<2>, cudaFuncAttributeMaxDynamicSharedMemorySize, GEMM_SMEM_BYTES);

    // 0) pre-round x + weights to tf32
    round_all_kernel<<<(RTOT + 255) / 256, 256>>>(
        (const float4*)x, (const float4*)W1, (const float4*)W2,
        (const float4*)WD, (const float4*)Wf,
        (float4*)xt, (float4*)w1t, (float4*)w2t, (float4*)wdt, (float4*)wft);

    // 1) a_pre = x@W1 + b1
    tc_gemm<0><<<dim3(HDIM/128, ROWS/128), 256, GEMM_SMEM_BYTES>>>(
        xt, w1t, b1, nullptr, apre, ROWS, HDIM, DIM);
    // 2) g = silu(x@W2 + b2)
    tc_gemm<1><<<dim3(HDIM/128, ROWS/128), 256, GEMM_SMEM_BYTES>>>(
        xt, w2t, b2, nullptr, gg, ROWS, HDIM, DIM);
    // 3) a = silu(conv(a_pre)); aat/agt rounded; out2 = a[...,1:]
    conv_fuse_kernel<<<(ROWS*HDIM)/256, 256>>>(apre, cw, cb, gg, aa, aat, agt, out + OUT2_OFF);
    // 4) delta = softplus(Dvec + a@WD + bD)
    tc_gemm<2><<<dim3(HDIM/128, ROWS/128), 256, GEMM_SMEM_BYTES>>>(
        aat, wdt, bD, Dv, dl, ROWS, HDIM, HDIM);
    // 5) Bm = a@WB + bB
    wb_kernel<<<ROWS/8, 256>>>(aa, WB, bB, bm);
    // 6) output = (a*g)@Wf + bf
    tc_gemm<0><<<dim3(DIM/128, ROWS/128), 256, GEMM_SMEM_BYTES>>>(
        agt, wft, bf, nullptr, out + OUT0_OFF, ROWS, DIM, HDIM);
    // 7) hid via fused selective scan
    scan_kernel<<<(BSZ*HDIM)/16, 256>>>(dl, aa, bm, A, out + OUT1_OFF);
}

// round 5
// speedup vs baseline: 2.5127x; 1.0705x over previous
#include <cuda_runtime.h>
#include <math.h>
#include <stdint.h>

// ---------------- problem constants ----------------
#define BSZ    2
#define LEN    2048
#define DIM    768
#define HDIM   1536
#define DSTATE 16
#define ROWS   (BSZ*LEN)   // 4096

#define OUT0_OFF 0
#define OUT1_OFF ((size_t)ROWS*DIM)
#define OUT2_OFF (OUT1_OFF + (size_t)ROWS*HDIM*DSTATE)

// ---------------- scratch ----------------
__device__ float g_apre[ROWS * HDIM];
__device__ float g_g   [ROWS * HDIM];
__device__ float g_a   [ROWS * HDIM];
__device__ float g_aat [ROWS * HDIM];
__device__ float g_agt [ROWS * HDIM];
__device__ float g_dl  [ROWS * HDIM];
__device__ float g_bm  [ROWS * DSTATE];
__device__ float g_xt  [ROWS * DIM];
__device__ float g_w1t [DIM * HDIM];
__device__ float g_w2t [DIM * HDIM];
__device__ float g_wdt [HDIM * HDIM];
__device__ float g_wft [HDIM * DIM];

// ---------------- PTX helpers ----------------
__device__ __forceinline__ uint32_t smem_u32(const void* p) {
    uint32_t a;
    asm("{ .reg .u64 t; cvta.to.shared.u64 t, %1; cvt.u32.u64 %0, t; }"
        : "=r"(a) : "l"(p));
    return a;
}
#define CP_ASYNC16(dst, src) \
    asm volatile("cp.async.cg.shared.global [%0], [%1], 16;" :: "r"(dst), "l"(src) : "memory")
#define CP_COMMIT()  asm volatile("cp.async.commit_group;" ::: "memory")
#define CP_WAIT2()   asm volatile("cp.async.wait_group 2;" ::: "memory")

__device__ __forceinline__ float rnd_tf32(float f) {
    uint32_t u;
    asm("cvt.rna.tf32.f32 %0, %1;" : "=r"(u) : "f"(f));
    return __uint_as_float(u);
}
__device__ __forceinline__ void mma_tf32(float* c, const uint32_t* a, const uint32_t* b) {
    asm volatile(
        "mma.sync.aligned.m16n8k8.row.col.f32.tf32.tf32.f32 "
        "{%0,%1,%2,%3}, {%4,%5,%6,%7}, {%8,%9}, {%0,%1,%2,%3};"
        : "+f"(c[0]), "+f"(c[1]), "+f"(c[2]), "+f"(c[3])
        : "r"(a[0]), "r"(a[1]), "r"(a[2]), "r"(a[3]), "r"(b[0]), "r"(b[1]));
}

// ---------------- pre-round x + all weights to tf32 ----------------
#define XT4  (ROWS*DIM/4)
#define W14  (DIM*HDIM/4)
#define WD4  (HDIM*HDIM/4)
#define RB0  XT4
#define RB1  (RB0 + W14)
#define RB2  (RB1 + W14)
#define RB3  (RB2 + WD4)
#define RTOT (RB3 + W14)

__global__ void __launch_bounds__(256) round_all_kernel(
    const float4* __restrict__ x,  const float4* __restrict__ w1,
    const float4* __restrict__ w2, const float4* __restrict__ wd,
    const float4* __restrict__ wf,
    float4* __restrict__ xt,  float4* __restrict__ w1t,
    float4* __restrict__ w2t, float4* __restrict__ wdt,
    float4* __restrict__ wft)
{
    int i = blockIdx.x * 256 + threadIdx.x;
    if (i >= RTOT) return;
    const float4* s; float4* d; int off;
    if      (i < RB0) { s = x;  d = xt;  off = i; }
    else if (i < RB1) { s = w1; d = w1t; off = i - RB0; }
    else if (i < RB2) { s = w2; d = w2t; off = i - RB1; }
    else if (i < RB3) { s = wd; d = wdt; off = i - RB2; }
    else              { s = wf; d = wft; off = i - RB3; }
    float4 v = s[off];
    v.x = rnd_tf32(v.x); v.y = rnd_tf32(v.y);
    v.z = rnd_tf32(v.z); v.w = rnd_tf32(v.w);
    d[off] = v;
}

// ---------------- TF32 tensor-core GEMM ----------------
// 128x128 CTA tile, 4 warps (64x64 each), 3-stage cp.async pipeline.
// C[M,N] = act(A[M,K] @ B[K,N] + bias (+bias2)); MODE 0 id, 1 silu, 2 softplus
#define BK 32
#define ASTRIDE 36
#define BSTRIDE 136
#define A_FLOATS (128 * ASTRIDE)                 // 4608
#define STAGE_FLOATS (A_FLOATS + BK * BSTRIDE)   // 8960
#define GEMM_SMEM_BYTES (3 * STAGE_FLOATS * 4)   // 107520

template<int MODE>
__global__ void __launch_bounds__(128, 2) tc_gemm(
    const float* __restrict__ A, const float* __restrict__ B,
    const float* __restrict__ bias, const float* __restrict__ bias2,
    float* __restrict__ C, int M, int N, int K)
{
    extern __shared__ float smem[];
    const uint32_t smem_b = smem_u32(smem);
    const int tid = threadIdx.x;
    const int wid = tid >> 5, lane = tid & 31;
    const int wm = wid >> 1, wn = wid & 1;      // 2x2 warp grid, 64x64 warp tile
    const int g = lane >> 2, t = lane & 3;
    const int bm = blockIdx.y * 128, bn = blockIdx.x * 128;

    auto load_tile = [&](int t0, int s) {
        const int k0 = t0 * BK;
        const uint32_t abase = smem_b + (uint32_t)s * (STAGE_FLOATS * 4);
        const uint32_t bbase = abase + A_FLOATS * 4;
        #pragma unroll
        for (int i = 0; i < 8; i++) {            // A: 128x32 floats, 1024 chunks
            int idx = i * 128 + tid;
            int r = idx >> 3, c4 = idx & 7;
            CP_ASYNC16(abase + (uint32_t)(r * ASTRIDE + c4 * 4) * 4,
                       A + (size_t)(bm + r) * K + k0 + c4 * 4);
        }
        #pragma unroll
        for (int i = 0; i < 8; i++) {            // B: 32x128 floats
            int idx = i * 128 + tid;
            int kk = idx >> 5, c4 = idx & 31;
            CP_ASYNC16(bbase + (uint32_t)(kk * BSTRIDE + c4 * 4) * 4,
                       B + (size_t)(k0 + kk) * N + bn + c4 * 4);
        }
    };

    float acc[4][8][4];
    #pragma unroll
    for (int mi = 0; mi < 4; mi++)
        #pragma unroll
        for (int nj = 0; nj < 8; nj++)
            #pragma unroll
            for (int q = 0; q < 4; q++) acc[mi][nj][q] = 0.f;

    const int T = K / BK;
    load_tile(0, 0); CP_COMMIT();
    load_tile(1, 1); CP_COMMIT();

    int s_cur = 0, s_nxt = 2;
    for (int tt = 0; tt < T; tt++) {
        if (tt + 2 < T) load_tile(tt + 2, s_nxt);
        CP_COMMIT();
        CP_WAIT2();
        __syncthreads();

        const float* As = smem + s_cur * STAGE_FLOATS;
        const float* Bs = As + A_FLOATS;

        #pragma unroll
        for (int kk = 0; kk < 4; kk++) {
            uint32_t af[4][4];
            #pragma unroll
            for (int mi = 0; mi < 4; mi++) {
                const float* ap = As + (wm * 64 + mi * 16 + g) * ASTRIDE + kk * 8 + t;
                af[mi][0] = __float_as_uint(ap[0]);
                af[mi][1] = __float_as_uint(ap[8 * ASTRIDE]);
                af[mi][2] = __float_as_uint(ap[4]);
                af[mi][3] = __float_as_uint(ap[8 * ASTRIDE + 4]);
            }
            uint32_t bf[8][2];
            #pragma unroll
            for (int nj = 0; nj < 8; nj++) {
                const float* bp = Bs + (kk * 8 + t) * BSTRIDE + wn * 64 + nj * 8 + g;
                bf[nj][0] = __float_as_uint(bp[0]);
                bf[nj][1] = __float_as_uint(bp[4 * BSTRIDE]);
            }
            #pragma unroll
            for (int mi = 0; mi < 4; mi++)
                #pragma unroll
                for (int nj = 0; nj < 8; nj++)
                    mma_tf32(acc[mi][nj], af[mi], bf[nj]);
        }
        __syncthreads();
        s_cur = (s_cur == 2) ? 0 : s_cur + 1;
        s_nxt = (s_nxt == 2) ? 0 : s_nxt + 1;
    }

    // epilogue
    #pragma unroll
    for (int nj = 0; nj < 8; nj++) {
        const int col = bn + wn * 64 + nj * 8 + t * 2;
        const float bz0 = __ldg(bias + col), bz1 = __ldg(bias + col + 1);
        const float e0 = (MODE == 2) ? __ldg(bias2 + col) : 0.f;
        const float e1 = (MODE == 2) ? __ldg(bias2 + col + 1) : 0.f;
        #pragma unroll
        for (int mi = 0; mi < 4; mi++) {
            const int row0 = bm + wm * 64 + mi * 16 + g;
            float v[4];
            v[0] = acc[mi][nj][0] + bz0 + e0;
            v[1] = acc[mi][nj][1] + bz1 + e1;
            v[2] = acc[mi][nj][2] + bz0 + e0;
            v[3] = acc[mi][nj][3] + bz1 + e1;
            #pragma unroll
            for (int q = 0; q < 4; q++) {
                if (MODE == 1) v[q] = v[q] / (1.f + expf(-v[q]));
                if (MODE == 2) v[q] = fmaxf(v[q], 0.f) + log1pf(expf(-fabsf(v[q])));
            }
            *(float2*)(C + (size_t)row0 * N + col)       = make_float2(v[0], v[1]);
            *(float2*)(C + (size_t)(row0 + 8) * N + col) = make_float2(v[2], v[3]);
        }
    }
}

// ---------------- conv(K=4)+silu; writes a, tf32(a), tf32(a*g), slice ------
__global__ void __launch_bounds__(256) conv_fuse_kernel(
    const float* __restrict__ apre, const float* __restrict__ cw,
    const float* __restrict__ cb, const float* __restrict__ g,
    float* __restrict__ aa, float* __restrict__ aat,
    float* __restrict__ agt, float* __restrict__ out2)
{
    const int idx = blockIdx.x * 256 + threadIdx.x;
    const int d = idx % HDIM;
    const int r = idx / HDIM;
    const int l = r & (LEN - 1);
    float s = cb[d];
    #pragma unroll
    for (int j = 0; j < 4; j++) {
        const int ll = l - 3 + j;
        if (ll >= 0)
            s = fmaf(apre[(size_t)(r - 3 + j) * HDIM + d], cw[d * 4 + j], s);
    }
    const float a = s / (1.f + expf(-s));
    aa[idx]  = a;
    aat[idx] = rnd_tf32(a);
    agt[idx] = rnd_tf32(a * g[idx]);
    if (d >= 1) out2[(size_t)r * (HDIM - 1) + d - 1] = a;
}

// ---------------- Bm = a @ WB + bB ----------------
__global__ void __launch_bounds__(256) wb_kernel(
    const float* __restrict__ a, const float* __restrict__ WB,
    const float* __restrict__ bB, float* __restrict__ Bm)
{
    const int wid = threadIdx.x >> 5, lane = threadIdx.x & 31;
    const int r = blockIdx.x * 8 + wid;
    const float* ar = a + (size_t)r * HDIM;
    float acc[16];
    #pragma unroll
    for (int s = 0; s < 16; s++) acc[s] = 0.f;
    for (int k = lane; k < HDIM; k += 32) {
        const float av = ar[k];
        const float4* w = (const float4*)(WB + (size_t)k * 16);
        float4 w0 = w[0], w1 = w[1], w2 = w[2], w3 = w[3];
        acc[0]  = fmaf(av, w0.x, acc[0]);  acc[1]  = fmaf(av, w0.y, acc[1]);
        acc[2]  = fmaf(av, w0.z, acc[2]);  acc[3]  = fmaf(av, w0.w, acc[3]);
        acc[4]  = fmaf(av, w1.x, acc[4]);  acc[5]  = fmaf(av, w1.y, acc[5]);
        acc[6]  = fmaf(av, w1.z, acc[6]);  acc[7]  = fmaf(av, w1.w, acc[7]);
        acc[8]  = fmaf(av, w2.x, acc[8]);  acc[9]  = fmaf(av, w2.y, acc[9]);
        acc[10] = fmaf(av, w2.z, acc[10]); acc[11] = fmaf(av, w2.w, acc[11]);
        acc[12] = fmaf(av, w3.x, acc[12]); acc[13] = fmaf(av, w3.y, acc[13]);
        acc[14] = fmaf(av, w3.z, acc[14]); acc[15] = fmaf(av, w3.w, acc[15]);
    }
    #pragma unroll
    for (int off = 16; off >= 1; off >>= 1)
        #pragma unroll
        for (int s = 0; s < 16; s++)
            acc[s] += __shfl_xor_sync(0xFFFFFFFF, acc[s], off);
    if (lane < 16) Bm[r * 16 + lane] = acc[lane] + bB[lane];
}

// ---------------- fused selective scan -> hid (streaming stores) -----------
__global__ void __launch_bounds__(256) scan_kernel(
    const float* __restrict__ delta, const float* __restrict__ a,
    const float* __restrict__ Bm, const float* __restrict__ A,
    float* __restrict__ hid)
{
    const int g = blockIdx.x * 16 + (threadIdx.x >> 4);
    const int s = threadIdx.x & 15;
    const int b = g / HDIM;
    const int d = g % HDIM;

    const float Ae = expf(-A[d * DSTATE + s]);
    float h = 0.f;

    const float* dptr = delta + (size_t)b * LEN * HDIM + d;
    const float* aptr = a     + (size_t)b * LEN * HDIM + d;
    const float* bptr = Bm    + (size_t)b * LEN * DSTATE + s;
    float* hptr = hid + ((size_t)b * LEN * HDIM + d) * DSTATE + s;

    for (int l0 = 0; l0 < LEN; l0 += 8) {
        float dv[8], av[8], bv[8];
        #pragma unroll
        for (int u = 0; u < 8; u++) {
            dv[u] = dptr[(size_t)(l0 + u) * HDIM];
            av[u] = aptr[(size_t)(l0 + u) * HDIM];
            bv[u] = bptr[(size_t)(l0 + u) * DSTATE];
        }
        #pragma unroll
        for (int u = 0; u < 8; u++) {
            h = fmaf(Ae * dv[u], h, bv[u] * dv[u] * av[u]);
            __stcs(hptr + (size_t)(l0 + u) * (HDIM * DSTATE), h);
        }
    }
}

// ---------------------------------------------------------------------------
extern "C" void kernel_launch(void* const* d_in, const int* in_sizes, int n_in,
                              void* d_out, int out_size)
{
    const float* x  = (const float*)d_in[0];
    const float* W1 = (const float*)d_in[1];
    const float* b1 = (const float*)d_in[2];
    const float* W2 = (const float*)d_in[3];
    const float* b2 = (const float*)d_in[4];
    const float* cw = (const float*)d_in[5];
    const float* cb = (const float*)d_in[6];
    const float* Wf = (const float*)d_in[7];
    const float* bf = (const float*)d_in[8];
    const float* A  = (const float*)d_in[9];
    const float* WB = (const float*)d_in[10];
    const float* bB = (const float*)d_in[11];
    const float* WD = (const float*)d_in[14];
    const float* bD = (const float*)d_in[15];
    const float* Dv = (const float*)d_in[16];

    float* out = (float*)d_out;

    float *apre, *gg, *aa, *aat, *agt, *dl, *bm;
    float *xt, *w1t, *w2t, *wdt, *wft;
    cudaGetSymbolAddress((void**)&apre, g_apre);
    cudaGetSymbolAddress((void**)&gg,   g_g);
    cudaGetSymbolAddress((void**)&aa,   g_a);
    cudaGetSymbolAddress((void**)&aat,  g_aat);
    cudaGetSymbolAddress((void**)&agt,  g_agt);
    cudaGetSymbolAddress((void**)&dl,   g_dl);
    cudaGetSymbolAddress((void**)&bm,   g_bm);
    cudaGetSymbolAddress((void**)&xt,   g_xt);
    cudaGetSymbolAddress((void**)&w1t,  g_w1t);
    cudaGetSymbolAddress((void**)&w2t,  g_w2t);
    cudaGetSymbolAddress((void**)&wdt,  g_wdt);
    cudaGetSymbolAddress((void**)&wft,  g_wft);

    cudaFuncSetAttribute(tc_gemm<0>, cudaFuncAttributeMaxDynamicSharedMemorySize, GEMM_SMEM_BYTES);
    cudaFuncSetAttribute(tc_gemm<1>, cudaFuncAttributeMaxDynamicSharedMemorySize, GEMM_SMEM_BYTES);
    cudaFuncSetAttribute(tc_gemm<2>, cudaFuncAttributeMaxDynamicSharedMemorySize, GEMM_SMEM_BYTES);

    round_all_kernel<<<(RTOT + 255) / 256, 256>>>(
        (const float4*)x, (const float4*)W1, (const float4*)W2,
        (const float4*)WD, (const float4*)Wf,
        (float4*)xt, (float4*)w1t, (float4*)w2t, (float4*)wdt, (float4*)wft);

    tc_gemm<0><<<dim3(HDIM/128, ROWS/128), 128, GEMM_SMEM_BYTES>>>(
        xt, w1t, b1, nullptr, apre, ROWS, HDIM, DIM);
    tc_gemm<1><<<dim3(HDIM/128, ROWS/128), 128, GEMM_SMEM_BYTES>>>(
        xt, w2t, b2, nullptr, gg, ROWS, HDIM, DIM);
    conv_fuse_kernel<<<(ROWS*HDIM)/256, 256>>>(apre, cw, cb, gg, aa, aat, agt, out + OUT2_OFF);
    tc_gemm<2><<<dim3(HDIM/128, ROWS/128), 128, GEMM_SMEM_BYTES>>>(
        aat, wdt, bD, Dv, dl, ROWS, HDIM, HDIM);
    wb_kernel<<<ROWS/8, 256>>>(aa, WB, bB, bm);
    tc_gemm<0><<<dim3(DIM/128, ROWS/128), 128, GEMM_SMEM_BYTES>>>(
        agt, wft, bf, nullptr, out + OUT0_OFF, ROWS, DIM, HDIM);
    scan_kernel<<<(BSZ*HDIM)/16, 256>>>(dl, aa, bm, A, out + OUT1_OFF);
}